// round 2
// baseline (speedup 1.0000x reference)
#include <cuda_runtime.h>
#include <cuda_bf16.h>

// SimpleLSTM: T=2048, B=1024, I=4, H=10, O=4
// Layout: 10 lanes per batch chain (one lane per hidden unit), 3 chains per warp.
// h broadcast across the chain's 10 lanes via __shfl_sync each step.

#define TT 2048
#define BB 1024
#define II 4
#define HH 10
#define OO 4
#define PF 4  // x prefetch depth (power of 2)

__device__ __forceinline__ float sigmoid_f(float v) {
    float e = __expf(-v);
    return __fdividef(1.0f, 1.0f + e);
}
__device__ __forceinline__ float tanh_f(float v) {
    float e = __expf(-2.0f * v);
    return __fdividef(2.0f, 1.0f + e) - 1.0f;
}

__global__ void __launch_bounds__(32, 1) lstm_kernel(
    const float* __restrict__ x,
    const float* __restrict__ h0,
    const float* __restrict__ c0,
    const float* __restrict__ W_ih,
    const float* __restrict__ W_hh,
    const float* __restrict__ b_ih,
    const float* __restrict__ b_hh,
    const float* __restrict__ W_fc,
    const float* __restrict__ b_fc,
    float* __restrict__ out,
    int out_size)
{
    const int lane  = threadIdx.x;            // 0..31
    const int group = lane / HH;              // 0..2 valid, 3 = idle lanes 30,31
    const int j     = lane - group * HH;      // hidden unit 0..9
    const int b     = blockIdx.x * 3 + group; // batch chain
    const bool lane_ok = (lane < 3 * HH);
    const bool active  = lane_ok && (b < BB);
    const int bc = (active ? b : (BB - 1));   // clamped for safe addressing

    // ---- per-lane weights: rows {j, 10+j, 20+j, 30+j} of the 4H gate matrices
    float wih[4][II];
    float whh[4][HH];
    float bias[4];
#pragma unroll
    for (int k = 0; k < 4; k++) {
        const int row = k * HH + j;
        bias[k] = b_ih[row] + b_hh[row];
#pragma unroll
        for (int i = 0; i < II; i++) wih[k][i] = W_ih[row * II + i];
#pragma unroll
        for (int jj = 0; jj < HH; jj++) whh[k][jj] = W_hh[row * HH + jj];
    }
    // fc weights: only lanes j<O use them (others load row 0, unused)
    const int jr = (j < OO) ? j : 0;
    float wfc[HH];
#pragma unroll
    for (int jj = 0; jj < HH; jj++) wfc[jj] = W_fc[jr * HH + jj];
    const float bfc = b_fc[jr];

    // ---- state
    float c = c0[bc * HH + j];
    float h = h0[bc * HH + j];
    const int shfl_base = group * HH;
    float h_all[HH];
#pragma unroll
    for (int jj = 0; jj < HH; jj++)
        h_all[jj] = __shfl_sync(0xffffffffu, h, shfl_base + jj);

    // ---- x prefetch: element (t*B + bc), 16B per chain per step
    const float4* xb = reinterpret_cast<const float4*>(x) + bc;
    float4 xv[PF];
#pragma unroll
    for (int p = 0; p < PF; p++) xv[p] = xb[p * BB];

    float* __restrict__ outp = out;

#pragma unroll 4
    for (int t = 0; t < TT; t++) {
        const float4 xc = xv[t & (PF - 1)];
        {   // prefetch t+PF (clamped)
            int tn = t + PF;
            tn = (tn < TT) ? tn : (TT - 1);
            xv[t & (PF - 1)] = xb[tn * BB];
        }

        // gate pre-activations: bias + W_ih*x + W_hh*h  (2 accumulators per gate)
        float a[4];
#pragma unroll
        for (int k = 0; k < 4; k++) {
            float s0 = bias[k];
            float s1 = 0.0f;
            s0 = fmaf(wih[k][0], xc.x, s0);
            s1 = fmaf(wih[k][1], xc.y, s1);
            s0 = fmaf(wih[k][2], xc.z, s0);
            s1 = fmaf(wih[k][3], xc.w, s1);
#pragma unroll
            for (int jj = 0; jj < HH; jj += 2) {
                s0 = fmaf(whh[k][jj],     h_all[jj],     s0);
                s1 = fmaf(whh[k][jj + 1], h_all[jj + 1], s1);
            }
            a[k] = s0 + s1;
        }

        const float ig = sigmoid_f(a[0]);
        const float fg = sigmoid_f(a[1]);
        const float gg = tanh_f(a[2]);
        const float og = sigmoid_f(a[3]);

        c = fmaf(fg, c, ig * gg);
        h = og * tanh_f(c);

        // broadcast new h across the chain's lanes
#pragma unroll
        for (int jj = 0; jj < HH; jj++)
            h_all[jj] = __shfl_sync(0xffffffffu, h, shfl_base + jj);

        // fused output projection: lanes j<O emit out[t, b, j]
        float val = bfc;
#pragma unroll
        for (int jj = 0; jj < HH; jj++)
            val = fmaf(wfc[jj], h_all[jj], val);
        if (active && j < OO)
            outp[(size_t)(t * BB + b) * OO + j] = val;
    }

    // final (hT, cT) tails, if the output buffer includes them
    const int main_sz = TT * BB * OO;
    if (out_size >= main_sz + 2 * BB * HH && active) {
        outp[main_sz + b * HH + j]           = h;
        outp[main_sz + BB * HH + b * HH + j] = c;
    }
}

extern "C" void kernel_launch(void* const* d_in, const int* in_sizes, int n_in,
                              void* d_out, int out_size)
{
    const float* x    = (const float*)d_in[0];
    const float* h0   = (const float*)d_in[1];
    const float* c0   = (const float*)d_in[2];
    const float* W_ih = (const float*)d_in[3];
    const float* W_hh = (const float*)d_in[4];
    const float* b_ih = (const float*)d_in[5];
    const float* b_hh = (const float*)d_in[6];
    const float* W_fc = (const float*)d_in[7];
    const float* b_fc = (const float*)d_in[8];
    float* out = (float*)d_out;

    const int nblocks = (BB + 2) / 3;  // 342 warps, 3 chains each
    lstm_kernel<<<nblocks, 32>>>(x, h0, c0, W_ih, W_hh, b_ih, b_hh,
                                 W_fc, b_fc, out, out_size);
}

// round 6
// speedup vs baseline: 1.3648x; 1.3648x over previous
#include <cuda_runtime.h>
#include <cuda_bf16.h>

// SimpleLSTM: T=2048, B=1024, I=4, H=10, O=4
// 10 lanes per batch chain (one per hidden unit), 3 chains per warp.
// R3: MUFU.TANH activations (sigmoid via 0.5*tanh(x/2)+0.5), x-part split
//     out of the h-dependent critical path.

#define TT 2048
#define BB 1024
#define II 4
#define HH 10
#define OO 4
#define PF 4  // x prefetch depth (power of 2)

__device__ __forceinline__ float tanh_fast(float x) {
    float r;
    asm("tanh.approx.f32 %0, %1;" : "=f"(r) : "f"(x));
    return r;
}
__device__ __forceinline__ float sigmoid_fast(float x) {
    return fmaf(0.5f, tanh_fast(0.5f * x), 0.5f);
}

__global__ void __launch_bounds__(32, 1) lstm_kernel(
    const float* __restrict__ x,
    const float* __restrict__ h0,
    const float* __restrict__ c0,
    const float* __restrict__ W_ih,
    const float* __restrict__ W_hh,
    const float* __restrict__ b_ih,
    const float* __restrict__ b_hh,
    const float* __restrict__ W_fc,
    const float* __restrict__ b_fc,
    float* __restrict__ out,
    int out_size)
{
    const int lane  = threadIdx.x;            // 0..31
    const int group = lane / HH;              // 0..2 valid, 3 = idle lanes 30,31
    const int j     = lane - group * HH;      // hidden unit 0..9
    const int b     = blockIdx.x * 3 + group; // batch chain
    const bool lane_ok = (lane < 3 * HH);
    const bool active  = lane_ok && (b < BB);
    const int bc = (active ? b : (BB - 1));   // clamped for safe addressing

    // per-lane weights: rows {j, 10+j, 20+j, 30+j} of the 4H gate matrices
    float wih[4][II];
    float whh[4][HH];
    float bias[4];
#pragma unroll
    for (int k = 0; k < 4; k++) {
        const int row = k * HH + j;
        bias[k] = b_ih[row] + b_hh[row];
#pragma unroll
        for (int i = 0; i < II; i++) wih[k][i] = W_ih[row * II + i];
#pragma unroll
        for (int jj = 0; jj < HH; jj++) whh[k][jj] = W_hh[row * HH + jj];
    }
    const int jr = (j < OO) ? j : 0;
    float wfc[HH];
#pragma unroll
    for (int jj = 0; jj < HH; jj++) wfc[jj] = W_fc[jr * HH + jj];
    const float bfc = b_fc[jr];

    // state
    float c = c0[bc * HH + j];
    float h = h0[bc * HH + j];
    const int shfl_base = group * HH;
    float h_all[HH];
#pragma unroll
    for (int jj = 0; jj < HH; jj++)
        h_all[jj] = __shfl_sync(0xffffffffu, h, shfl_base + jj);

    // x prefetch: element (t*B + bc), one float4 per chain per step
    const float4* xb = reinterpret_cast<const float4*>(x) + bc;
    float4 xv[PF];
#pragma unroll
    for (int p = 0; p < PF; p++) xv[p] = xb[p * BB];

    float* __restrict__ outp = out;

#pragma unroll 4
    for (int t = 0; t < TT; t++) {
        const float4 xc = xv[t & (PF - 1)];
        {   // prefetch t+PF (clamped)
            int tn = t + PF;
            tn = (tn < TT) ? tn : (TT - 1);
            xv[t & (PF - 1)] = xb[tn * BB];
        }

        // x-part of gates: independent of h, schedules into the shfl shadow
        float xa[4];
#pragma unroll
        for (int k = 0; k < 4; k++) {
            float s0 = fmaf(wih[k][0], xc.x, bias[k]);
            float s1 = wih[k][1] * xc.y;
            s0 = fmaf(wih[k][2], xc.z, s0);
            s1 = fmaf(wih[k][3], xc.w, s1);
            xa[k] = s0 + s1;
        }

        // h-part: 10-term dot per gate, 2 accumulators
        float a[4];
#pragma unroll
        for (int k = 0; k < 4; k++) {
            float s0 = xa[k];
            float s1 = 0.0f;
#pragma unroll
            for (int jj = 0; jj < HH; jj += 2) {
                s0 = fmaf(whh[k][jj],     h_all[jj],     s0);
                s1 = fmaf(whh[k][jj + 1], h_all[jj + 1], s1);
            }
            a[k] = s0 + s1;
        }

        const float ig = sigmoid_fast(a[0]);
        const float fg = sigmoid_fast(a[1]);
        const float gg = tanh_fast(a[2]);
        const float og = sigmoid_fast(a[3]);

        c = fmaf(fg, c, ig * gg);
        h = og * tanh_fast(c);

        // broadcast new h across the chain's lanes
#pragma unroll
        for (int jj = 0; jj < HH; jj++)
            h_all[jj] = __shfl_sync(0xffffffffu, h, shfl_base + jj);

        // fused output projection: lanes j<O emit out[t, b, j]
        float v0 = bfc, v1 = 0.0f;
#pragma unroll
        for (int jj = 0; jj < HH; jj += 2) {
            v0 = fmaf(wfc[jj],     h_all[jj],     v0);
            v1 = fmaf(wfc[jj + 1], h_all[jj + 1], v1);
        }
        if (active && j < OO)
            outp[(size_t)(t * BB + b) * OO + j] = v0 + v1;
    }

    // final (hT, cT) tails, if the output buffer includes them
    const int main_sz = TT * BB * OO;
    if (out_size >= main_sz + 2 * BB * HH && active) {
        outp[main_sz + b * HH + j]           = h;
        outp[main_sz + BB * HH + b * HH + j] = c;
    }
}

extern "C" void kernel_launch(void* const* d_in, const int* in_sizes, int n_in,
                              void* d_out, int out_size)
{
    const float* x    = (const float*)d_in[0];
    const float* h0   = (const float*)d_in[1];
    const float* c0   = (const float*)d_in[2];
    const float* W_ih = (const float*)d_in[3];
    const float* W_hh = (const float*)d_in[4];
    const float* b_ih = (const float*)d_in[5];
    const float* b_hh = (const float*)d_in[6];
    const float* W_fc = (const float*)d_in[7];
    const float* b_fc = (const float*)d_in[8];
    float* out = (float*)d_out;

    const int nblocks = (BB + 2) / 3;  // 342 warps, 3 chains each
    lstm_kernel<<<nblocks, 32>>>(x, h0, c0, W_ih, W_hh, b_ih, b_hh,
                                 W_fc, b_fc, out, out_size);
}